// round 3
// baseline (speedup 1.0000x reference)
#include <cuda_runtime.h>
#include <cstdint>
#include <cstddef>

#define BB      8192
#define IN_DIM  1024
#define H_DIM   1024
#define OUT_DIM 512
#define KBIG    (IN_DIM + H_DIM)

// ---------- scratch (__device__ globals: allocation-guard-safe) ----------------
// All GEMM operands live here RNA-rounded to tf32 values AND K-permuted within
// each 8-col group by order [0,4,1,5,2,6,3,7] so mma fragments load as LDS.64.
__device__ float g_x  [BB * IN_DIM];
__device__ float g_h  [BB * H_DIM];
__device__ float g_wz [H_DIM * KBIG];
__device__ float g_wr [H_DIM * KBIG];
__device__ float g_wh [H_DIM * KBIG];
__device__ float g_wo [OUT_DIM * H_DIM];
__device__ float g_z  [BB * H_DIM];     // sigmoid(z), canonical layout
__device__ float g_rh [BB * H_DIM];     // r*h, rounded + permuted (GEMM A operand)
__device__ float g_hid[BB * H_DIM];     // hidden, rounded + permuted (GEMM A operand)

// ---------- helpers ------------------------------------------------------------
__device__ __forceinline__ uint32_t smem_u32(const void* p) {
    uint32_t a;
    asm("{ .reg .u64 t; cvta.to.shared.u64 t, %1; cvt.u32.u64 %0, t; }" : "=r"(a) : "l"(p));
    return a;
}
__device__ __forceinline__ float rna_tf32(float f) {
    uint32_t r;
    asm("cvt.rna.tf32.f32 %0, %1;" : "=r"(r) : "f"(f));
    return __uint_as_float(r);
}
__device__ __forceinline__ float sigmoidf_(float x) { return 1.0f / (1.0f + expf(-x)); }

__device__ __forceinline__ void cp16(uint32_t dst, const void* src) {
    asm volatile("cp.async.cg.shared.global [%0], [%1], 16;" :: "r"(dst), "l"(src));
}
__device__ __forceinline__ void mma816(float* c, float2 al, float2 ah, float2 b) {
    asm volatile(
        "mma.sync.aligned.m16n8k8.row.col.f32.tf32.tf32.f32 "
        "{%0,%1,%2,%3}, {%4,%5,%6,%7}, {%8,%9}, {%0,%1,%2,%3};"
        : "+f"(c[0]), "+f"(c[1]), "+f"(c[2]), "+f"(c[3])
        : "r"(__float_as_uint(al.x)), "r"(__float_as_uint(ah.x)),
          "r"(__float_as_uint(al.y)), "r"(__float_as_uint(ah.y)),
          "r"(__float_as_uint(b.x)),  "r"(__float_as_uint(b.y)));
}

// ---------- prep: RNA-round + K-permute ([0,4,1,5,2,6,3,7] per 8-group) --------
template<int WHICH>
__global__ void round_perm(const float* __restrict__ src, int n8) {
    float* dst;
    if      (WHICH == 0) dst = g_x;
    else if (WHICH == 1) dst = g_h;
    else if (WHICH == 2) dst = g_wz;
    else if (WHICH == 3) dst = g_wr;
    else if (WHICH == 4) dst = g_wh;
    else                 dst = g_wo;
    int i = blockIdx.x * blockDim.x + threadIdx.x;
    if (i < n8) {
        float4 a = ((const float4*)src)[2 * i];
        float4 b = ((const float4*)src)[2 * i + 1];
        float4 o0 = { rna_tf32(a.x), rna_tf32(b.x), rna_tf32(a.y), rna_tf32(b.y) };
        float4 o1 = { rna_tf32(a.z), rna_tf32(b.z), rna_tf32(a.w), rna_tf32(b.w) };
        ((float4*)dst)[2 * i]     = o0;
        ((float4*)dst)[2 * i + 1] = o1;
    }
}

// ---------- HMMA GEMM + fused GRU epilogue -------------------------------------
// CTA tile 128x128, 8 warps (4 m-warps x 2 n-warps), warp tile 32x64.
// K staged in 32-float chunks, 2-stage cp.async pipeline.
// Smem row stride 40 floats: conflict-free LDS.64 fragments + STS.128 stores.
#define ROWSTR   40
#define A_HALF_F (128 * ROWSTR)                 // 5120 floats
#define STAGE_F  (2 * A_HALF_F)                 // 10240 floats (A + B)
#define SMEM_BYTES (2 * STAGE_F * 4)            // 81920 bytes

template<int MODE>
__global__ __launch_bounds__(256, 2)
void hgemm(const float* __restrict__ hprev, const float* __restrict__ bias,
           float* __restrict__ out)
{
    constexpr int KTOT = (MODE == 3) ? H_DIM : KBIG;
    constexpr int NC   = KTOT / 32;

    extern __shared__ float smem[];
    const uint32_t sbase = smem_u32(smem);

    const int tid    = threadIdx.x;
    const int lane   = tid & 31;
    const int warp   = tid >> 5;
    const int warp_m = warp & 3;
    const int warp_n = warp >> 2;
    const int gid    = lane >> 2;
    const int tig    = lane & 3;
    const int blockRow = blockIdx.y * 128;
    const int blockCol = blockIdx.x * 128;

    const float* W;
    if      (MODE == 0) W = g_wz;
    else if (MODE == 1) W = g_wr;
    else if (MODE == 2) W = g_wh;
    else                W = g_wo;

    float acc[2][8][4];
    #pragma unroll
    for (int mi = 0; mi < 2; mi++)
        #pragma unroll
        for (int ni = 0; ni < 8; ni++)
            #pragma unroll
            for (int e = 0; e < 4; e++) acc[mi][ni][e] = 0.0f;

    auto load_stage = [&](int chunk) {
        const int s = chunk & 1;
        const uint32_t abase = sbase + (uint32_t)(s * STAGE_F) * 4;
        const uint32_t bbase = abase + A_HALF_F * 4;
        int koff = chunk * 32;
        const float* Asrc;
        if (MODE == 3)          { Asrc = g_hid; }
        else if (koff < IN_DIM) { Asrc = g_x; }
        else { Asrc = (MODE == 2) ? g_rh : g_h; koff -= IN_DIM; }
        #pragma unroll
        for (int i = 0; i < 4; i++) {                    // A: 1024 x 16B
            int idx = tid + i * 256;
            int r = idx >> 3, c = idx & 7;
            cp16(abase + (uint32_t)(r * ROWSTR + c * 4) * 4,
                 Asrc + (size_t)(blockRow + r) * 1024 + koff + c * 4);
        }
        #pragma unroll
        for (int i = 0; i < 4; i++) {                    // B(W): 1024 x 16B
            int idx = tid + i * 256;
            int r = idx >> 3, c = idx & 7;
            cp16(bbase + (uint32_t)(r * ROWSTR + c * 4) * 4,
                 W + (size_t)(blockCol + r) * KTOT + chunk * 32 + c * 4);
        }
        asm volatile("cp.async.commit_group;" ::: "memory");
    };

    load_stage(0);
    load_stage(1);

    for (int chunk = 0; chunk < NC; chunk++) {
        if (chunk + 1 < NC)
            asm volatile("cp.async.wait_group 1;" ::: "memory");
        else
            asm volatile("cp.async.wait_group 0;" ::: "memory");
        __syncthreads();

        const float* As = smem + (chunk & 1) * STAGE_F;
        const float* Bs = As + A_HALF_F;
        const int ar0 = (warp_m * 32 + gid) * ROWSTR;
        const int br0 = (warp_n * 64 + gid) * ROWSTR;

        #pragma unroll
        for (int ks = 0; ks < 4; ks++) {
            const int kc = ks * 8 + 2 * tig;
            float2 b[8];
            #pragma unroll
            for (int ni = 0; ni < 8; ni++)
                b[ni] = *(const float2*)&Bs[br0 + ni * 8 * ROWSTR + kc];
            #pragma unroll
            for (int mi = 0; mi < 2; mi++) {
                float2 al = *(const float2*)&As[ar0 + mi * 16 * ROWSTR + kc];
                float2 ah = *(const float2*)&As[ar0 + (mi * 16 + 8) * ROWSTR + kc];
                #pragma unroll
                for (int ni = 0; ni < 8; ni++)
                    mma816(acc[mi][ni], al, ah, b[ni]);
            }
        }
        __syncthreads();
        if (chunk + 2 < NC) load_stage(chunk + 2);
    }

    // ---------------- fused epilogue ------------------------------------------
    // D fragment: rows gid / gid+8, cols tig*2, tig*2+1 within each ni 8-group.
    // Permuted slots (for writing next-GEMM A operands): col 2t -> s0, 2t+1 -> s1.
    const int s0 = ((2 * tig) & 3) * 2 + (tig >> 1);          // 0,4,1,5
    const int s1 = ((2 * tig + 1) & 3) * 2 + ((2 * tig + 1) >> 2); // 2,6,3,7

    #pragma unroll
    for (int mi = 0; mi < 2; mi++) {
        #pragma unroll
        for (int ni = 0; ni < 8; ni++) {
            const int grp = blockCol + warp_n * 64 + ni * 8;   // 8-col group base
            const int col = grp + tig * 2;
            float2 bv = *(const float2*)(bias + col);
            #pragma unroll
            for (int half = 0; half < 2; half++) {
                const int row = blockRow + warp_m * 32 + mi * 16 + gid + half * 8;
                float v0 = acc[mi][ni][half * 2 + 0] + bv.x;
                float v1 = acc[mi][ni][half * 2 + 1] + bv.y;
                if (MODE == 0) {
                    *(float2*)(g_z + (size_t)row * H_DIM + col) =
                        make_float2(sigmoidf_(v0), sigmoidf_(v1));
                } else if (MODE == 1) {
                    float2 hv = *(const float2*)(hprev + (size_t)row * H_DIM + col);
                    float r0 = sigmoidf_(v0) * hv.x;
                    float r1 = sigmoidf_(v1) * hv.y;
                    g_rh[(size_t)row * H_DIM + grp + s0] = rna_tf32(r0);
                    g_rh[(size_t)row * H_DIM + grp + s1] = rna_tf32(r1);
                } else if (MODE == 2) {
                    float2 hv = *(const float2*)(hprev + (size_t)row * H_DIM + col);
                    float2 zv = *(const float2*)(g_z   + (size_t)row * H_DIM + col);
                    float h0 = (1.0f - zv.x) * hv.x + zv.x * tanhf(v0);
                    float h1 = (1.0f - zv.y) * hv.y + zv.y * tanhf(v1);
                    *(float2*)(out + (size_t)row * H_DIM + col) = make_float2(h0, h1);
                    g_hid[(size_t)row * H_DIM + grp + s0] = rna_tf32(h0);
                    g_hid[(size_t)row * H_DIM + grp + s1] = rna_tf32(h1);
                } else {
                    *(float2*)(out + (size_t)row * OUT_DIM + col) = make_float2(v0, v1);
                }
            }
        }
    }
}

// ---------- host ---------------------------------------------------------------
extern "C" void kernel_launch(void* const* d_in, const int* in_sizes, int n_in,
                              void* d_out, int out_size)
{
    const float* x  = (const float*)d_in[0];
    const float* h  = (const float*)d_in[1];
    const float* Wz = (const float*)d_in[2];
    const float* bz = (const float*)d_in[3];
    const float* Wr = (const float*)d_in[4];
    const float* br = (const float*)d_in[5];
    const float* Wh = (const float*)d_in[6];
    const float* bh = (const float*)d_in[7];
    const float* Wo = (const float*)d_in[8];
    const float* bo = (const float*)d_in[9];

    float* out_o = (float*)d_out;
    float* out_h = (float*)d_out + (size_t)BB * OUT_DIM;

    static bool attr_done = false;
    if (!attr_done) {
        cudaFuncSetAttribute(hgemm<0>, cudaFuncAttributeMaxDynamicSharedMemorySize, SMEM_BYTES);
        cudaFuncSetAttribute(hgemm<1>, cudaFuncAttributeMaxDynamicSharedMemorySize, SMEM_BYTES);
        cudaFuncSetAttribute(hgemm<2>, cudaFuncAttributeMaxDynamicSharedMemorySize, SMEM_BYTES);
        cudaFuncSetAttribute(hgemm<3>, cudaFuncAttributeMaxDynamicSharedMemorySize, SMEM_BYTES);
        attr_done = true;
    }

    // prep: round + permute all GEMM operands
    {
        int n8x = BB * IN_DIM / 8;        // 1,048,576
        int n8w = H_DIM * KBIG / 8;       // 262,144
        int n8o = OUT_DIM * H_DIM / 8;    // 65,536
        round_perm<0><<<(n8x + 255) / 256, 256>>>(x,  n8x);
        round_perm<1><<<(n8x + 255) / 256, 256>>>(h,  n8x);
        round_perm<2><<<(n8w + 255) / 256, 256>>>(Wz, n8w);
        round_perm<3><<<(n8w + 255) / 256, 256>>>(Wr, n8w);
        round_perm<4><<<(n8w + 255) / 256, 256>>>(Wh, n8w);
        round_perm<5><<<(n8o + 255) / 256, 256>>>(Wo, n8o);
    }

    dim3 blk(256);
    dim3 g1(H_DIM / 128, BB / 128);    // (8, 64)
    dim3 g3(OUT_DIM / 128, BB / 128);  // (4, 64)

    hgemm<0><<<g1, blk, SMEM_BYTES>>>(nullptr, bz, nullptr);  // z = sigmoid(xh Wz^T + bz)
    hgemm<1><<<g1, blk, SMEM_BYTES>>>(h,       br, nullptr);  // rh = sigmoid(.)*h (perm)
    hgemm<2><<<g1, blk, SMEM_BYTES>>>(h,       bh, out_h);    // hidden + perm copy
    hgemm<3><<<g3, blk, SMEM_BYTES>>>(nullptr, bo, out_o);    // output = hid Wo^T + bo
}

// round 4
// speedup vs baseline: 1.4219x; 1.4219x over previous
#include <cuda_runtime.h>
#include <cstdint>
#include <cstddef>

#define BB      8192
#define IN_DIM  1024
#define H_DIM   1024
#define OUT_DIM 512
#define KBIG    (IN_DIM + H_DIM)

// ---------- scratch (__device__ globals: allocation-guard-safe) ----------------
__device__ float g_z  [BB * H_DIM];     // sigmoid(z)
__device__ float g_rh [BB * H_DIM];     // r * h
__device__ float g_hid[BB * H_DIM];     // new hidden state (copy of out_h)

// ---------- helpers ------------------------------------------------------------
__device__ __forceinline__ uint32_t smem_u32(const void* p) {
    uint32_t a;
    asm("{ .reg .u64 t; cvta.to.shared.u64 t, %1; cvt.u32.u64 %0, t; }" : "=r"(a) : "l"(p));
    return a;
}
__device__ __forceinline__ uint32_t f2tf32(float f) {
    uint32_t r;
    asm("cvt.rna.tf32.f32 %0, %1;" : "=r"(r) : "f"(f));
    return r;
}
__device__ __forceinline__ float sigmoidf_(float x) { return 1.0f / (1.0f + expf(-x)); }

__device__ __forceinline__ void cp16(uint32_t dst, const void* src) {
    asm volatile("cp.async.cg.shared.global [%0], [%1], 16;" :: "r"(dst), "l"(src));
}

// trivial kernel so the profiler's fixed capture slot (launch idx 3) lands on
// the big MODE-2 GEMM: launch order = dummy, g0, g1, g2(big, captured), g3
__global__ void dummy_k() {}

// ---------- HMMA GEMM + fused GRU epilogue -------------------------------------
// CTA tile 128x128, 256 threads = 8 warps (4 m x 2 n), warp tile 32x64.
// K in 32-float chunks, 3-stage cp.async pipeline, ONE barrier per chunk.
#define ROWSTR   36
#define HALF_F   (128 * ROWSTR)                 // 4608 floats (A or B half)
#define STAGE_F  (2 * HALF_F)                   // 9216 floats
#define NSTAGE   3
#define SMEM_BYTES (NSTAGE * STAGE_F * 4)       // 110592 bytes

template<int MODE>
__global__ __launch_bounds__(256, 2)
void hgemm(const float* __restrict__ A0, const float* __restrict__ A1,
           const float* __restrict__ W,  const float* __restrict__ bias,
           const float* __restrict__ hprev, float* __restrict__ out)
{
    constexpr int KTOT = (MODE == 3) ? H_DIM : KBIG;
    constexpr int NC   = KTOT / 32;

    extern __shared__ float smem[];
    const uint32_t sbase = smem_u32(smem);

    const int tid    = threadIdx.x;
    const int lane   = tid & 31;
    const int warp   = tid >> 5;
    const int warp_m = warp & 3;
    const int warp_n = warp >> 2;
    const int gid    = lane >> 2;
    const int tig    = lane & 3;
    const int blockRow = blockIdx.y * 128;
    const int blockCol = blockIdx.x * 128;

    float acc[2][8][4];
    #pragma unroll
    for (int mi = 0; mi < 2; mi++)
        #pragma unroll
        for (int ni = 0; ni < 8; ni++)
            #pragma unroll
            for (int e = 0; e < 4; e++) acc[mi][ni][e] = 0.0f;

    auto load_stage = [&](int chunk, int s) {
        const uint32_t abase = sbase + (uint32_t)(s * STAGE_F) * 4;
        const uint32_t bbase = abase + HALF_F * 4;
        int koff = chunk * 32;
        const float* Asrc;
        if (MODE == 3)          { Asrc = A0; }
        else if (koff < IN_DIM) { Asrc = A0; }
        else                    { Asrc = A1; koff -= IN_DIM; }
        #pragma unroll
        for (int i = 0; i < 4; i++) {                    // A: 1024 x 16B
            int idx = tid + i * 256;
            int r = idx >> 3, c = idx & 7;
            cp16(abase + (uint32_t)(r * ROWSTR + c * 4) * 4,
                 Asrc + (size_t)(blockRow + r) * 1024 + koff + c * 4);
        }
        #pragma unroll
        for (int i = 0; i < 4; i++) {                    // B(W): 1024 x 16B
            int idx = tid + i * 256;
            int r = idx >> 3, c = idx & 7;
            cp16(bbase + (uint32_t)(r * ROWSTR + c * 4) * 4,
                 W + (size_t)(blockCol + r) * KTOT + chunk * 32 + c * 4);
        }
        asm volatile("cp.async.commit_group;" ::: "memory");
    };

    // prologue: 2 stages in flight
    load_stage(0, 0);
    load_stage(1, 1);

    int s_cur = 0;                 // stage of chunk c
    for (int chunk = 0; chunk < NC; chunk++) {
        if (chunk + 1 < NC)
            asm volatile("cp.async.wait_group 1;" ::: "memory");
        else
            asm volatile("cp.async.wait_group 0;" ::: "memory");
        __syncthreads();

        // kick off chunk+2 into the stage consumed at chunk-1 (freed by the barrier)
        if (chunk + 2 < NC) {
            int s_next = s_cur + 2;
            if (s_next >= NSTAGE) s_next -= NSTAGE;
            load_stage(chunk + 2, s_next);
        }

        const float* As = smem + s_cur * STAGE_F;
        const float* Bs = As + HALF_F;

        #pragma unroll
        for (int ks = 0; ks < 4; ks++) {
            const int k = ks * 8;
            uint32_t af[2][4];
            #pragma unroll
            for (int mi = 0; mi < 2; mi++) {
                int rb = warp_m * 32 + mi * 16;
                af[mi][0] = f2tf32(As[(rb + gid    ) * ROWSTR + k + tig    ]);
                af[mi][1] = f2tf32(As[(rb + gid + 8) * ROWSTR + k + tig    ]);
                af[mi][2] = f2tf32(As[(rb + gid    ) * ROWSTR + k + tig + 4]);
                af[mi][3] = f2tf32(As[(rb + gid + 8) * ROWSTR + k + tig + 4]);
            }
            uint32_t bf[8][2];
            #pragma unroll
            for (int ni = 0; ni < 8; ni++) {
                int cb = warp_n * 64 + ni * 8;
                bf[ni][0] = f2tf32(Bs[(cb + gid) * ROWSTR + k + tig    ]);
                bf[ni][1] = f2tf32(Bs[(cb + gid) * ROWSTR + k + tig + 4]);
            }
            #pragma unroll
            for (int mi = 0; mi < 2; mi++)
                #pragma unroll
                for (int ni = 0; ni < 8; ni++) {
                    asm volatile(
                        "mma.sync.aligned.m16n8k8.row.col.f32.tf32.tf32.f32 "
                        "{%0,%1,%2,%3}, {%4,%5,%6,%7}, {%8,%9}, {%0,%1,%2,%3};"
                        : "+f"(acc[mi][ni][0]), "+f"(acc[mi][ni][1]),
                          "+f"(acc[mi][ni][2]), "+f"(acc[mi][ni][3])
                        : "r"(af[mi][0]), "r"(af[mi][1]),
                          "r"(af[mi][2]), "r"(af[mi][3]),
                          "r"(bf[ni][0]), "r"(bf[ni][1]));
                }
        }

        s_cur++;
        if (s_cur == NSTAGE) s_cur = 0;
    }

    // ---------------- fused epilogue ------------------------------------------
    #pragma unroll
    for (int mi = 0; mi < 2; mi++) {
        #pragma unroll
        for (int ni = 0; ni < 8; ni++) {
            const int col = blockCol + warp_n * 64 + ni * 8 + tig * 2;
            float2 bv = *(const float2*)(bias + col);
            #pragma unroll
            for (int half = 0; half < 2; half++) {
                const int row = blockRow + warp_m * 32 + mi * 16 + gid + half * 8;
                float v0 = acc[mi][ni][half * 2 + 0] + bv.x;
                float v1 = acc[mi][ni][half * 2 + 1] + bv.y;
                if (MODE == 0) {
                    *(float2*)(g_z + (size_t)row * H_DIM + col) =
                        make_float2(sigmoidf_(v0), sigmoidf_(v1));
                } else if (MODE == 1) {
                    float2 hv = *(const float2*)(hprev + (size_t)row * H_DIM + col);
                    *(float2*)(g_rh + (size_t)row * H_DIM + col) =
                        make_float2(sigmoidf_(v0) * hv.x, sigmoidf_(v1) * hv.y);
                } else if (MODE == 2) {
                    float2 hv = *(const float2*)(hprev + (size_t)row * H_DIM + col);
                    float2 zv = *(const float2*)(g_z   + (size_t)row * H_DIM + col);
                    float h0 = (1.0f - zv.x) * hv.x + zv.x * tanhf(v0);
                    float h1 = (1.0f - zv.y) * hv.y + zv.y * tanhf(v1);
                    *(float2*)(out   + (size_t)row * H_DIM + col) = make_float2(h0, h1);
                    *(float2*)(g_hid + (size_t)row * H_DIM + col) = make_float2(h0, h1);
                } else {
                    *(float2*)(out + (size_t)row * OUT_DIM + col) = make_float2(v0, v1);
                }
            }
        }
    }
}

// ---------- host ---------------------------------------------------------------
extern "C" void kernel_launch(void* const* d_in, const int* in_sizes, int n_in,
                              void* d_out, int out_size)
{
    const float* x  = (const float*)d_in[0];
    const float* h  = (const float*)d_in[1];
    const float* Wz = (const float*)d_in[2];
    const float* bz = (const float*)d_in[3];
    const float* Wr = (const float*)d_in[4];
    const float* br = (const float*)d_in[5];
    const float* Wh = (const float*)d_in[6];
    const float* bh = (const float*)d_in[7];
    const float* Wo = (const float*)d_in[8];
    const float* bo = (const float*)d_in[9];

    float* out_o = (float*)d_out;
    float* out_h = (float*)d_out + (size_t)BB * OUT_DIM;

    static bool attr_done = false;
    if (!attr_done) {
        cudaFuncSetAttribute(hgemm<0>, cudaFuncAttributeMaxDynamicSharedMemorySize, SMEM_BYTES);
        cudaFuncSetAttribute(hgemm<1>, cudaFuncAttributeMaxDynamicSharedMemorySize, SMEM_BYTES);
        cudaFuncSetAttribute(hgemm<2>, cudaFuncAttributeMaxDynamicSharedMemorySize, SMEM_BYTES);
        cudaFuncSetAttribute(hgemm<3>, cudaFuncAttributeMaxDynamicSharedMemorySize, SMEM_BYTES);
        attr_done = true;
    }

    float* g_rh_p;  cudaGetSymbolAddress((void**)&g_rh_p,  g_rh);
    float* g_hid_p; cudaGetSymbolAddress((void**)&g_hid_p, g_hid);

    dim3 blk(256);
    dim3 g1(H_DIM / 128, BB / 128);    // (8, 64)
    dim3 g3(OUT_DIM / 128, BB / 128);  // (4, 64)

    dummy_k<<<1, 32>>>();   // pad so profiler's capture slot (idx 3) = big MODE-2 GEMM

    // z = sigmoid([x|h] Wz^T + bz)
    hgemm<0><<<g1, blk, SMEM_BYTES>>>(x, h, Wz, bz, nullptr, nullptr);
    // rh = sigmoid([x|h] Wr^T + br) * h
    hgemm<1><<<g1, blk, SMEM_BYTES>>>(x, h, Wr, br, h, nullptr);
    // hidden = (1-z)*h + z*tanh([x|rh] Wh^T + bh)   (captured by profiler)
    hgemm<2><<<g1, blk, SMEM_BYTES>>>(x, g_rh_p, Wh, bh, h, out_h);
    // output = hidden Wo^T + bo
    hgemm<3><<<g3, blk, SMEM_BYTES>>>(g_hid_p, nullptr, Wo, bo, nullptr, out_o);
}

// round 5
// speedup vs baseline: 1.4463x; 1.0171x over previous
#include <cuda_runtime.h>
#include <cstdint>
#include <cstddef>

#define BB      8192
#define IN_DIM  1024
#define H_DIM   1024
#define OUT_DIM 512
#define KBIG    (IN_DIM + H_DIM)

// ---------- scratch (__device__ globals: allocation-guard-safe) ----------------
__device__ float g_z  [BB * H_DIM];     // sigmoid(z)
__device__ float g_rh [BB * H_DIM];     // r * h
__device__ float g_hid[BB * H_DIM];     // new hidden state (copy of out_h)

// ---------- helpers ------------------------------------------------------------
__device__ __forceinline__ uint32_t smem_u32(const void* p) {
    uint32_t a;
    asm("{ .reg .u64 t; cvta.to.shared.u64 t, %1; cvt.u32.u64 %0, t; }" : "=r"(a) : "l"(p));
    return a;
}
__device__ __forceinline__ uint32_t f2tf32(float f) {
    uint32_t r;
    asm("cvt.rna.tf32.f32 %0, %1;" : "=r"(r) : "f"(f));
    return r;
}
__device__ __forceinline__ float sigmoidf_(float x) { return 1.0f / (1.0f + expf(-x)); }

__device__ __forceinline__ void cp16(uint32_t dst, const void* src) {
    asm volatile("cp.async.cg.shared.global [%0], [%1], 16;" :: "r"(dst), "l"(src));
}

// trivial kernel so the profiler's fixed capture slot (launch idx 3) lands on
// the big MODE-2 GEMM: launch order = dummy, g0, g1, g2(big, captured), g3
__global__ void dummy_k() {}

// ---------- HMMA GEMM + fused GRU epilogue -------------------------------------
// CTA tile 128x128, 128 threads = 4 warps (2 m x 2 n), warp tile 64x64.
// K in 32-float chunks, 3-stage cp.async pipeline, ONE barrier per chunk.
// Per k-step per warp: 32 LDS + 32 cvt feed 32 independent HMMA.
#define ROWSTR   36
#define HALF_F   (128 * ROWSTR)                 // 4608 floats (A or B half)
#define STAGE_F  (2 * HALF_F)                   // 9216 floats
#define NSTAGE   3
#define SMEM_BYTES (NSTAGE * STAGE_F * 4)       // 110592 bytes

template<int MODE>
__global__ __launch_bounds__(128, 2)
void hgemm(const float* __restrict__ A0, const float* __restrict__ A1,
           const float* __restrict__ W,  const float* __restrict__ bias,
           const float* __restrict__ hprev, float* __restrict__ out)
{
    constexpr int KTOT = (MODE == 3) ? H_DIM : KBIG;
    constexpr int NC   = KTOT / 32;

    extern __shared__ float smem[];
    const uint32_t sbase = smem_u32(smem);

    const int tid    = threadIdx.x;
    const int lane   = tid & 31;
    const int warp   = tid >> 5;
    const int warp_m = warp & 1;    // 2 m-warps * 64 rows
    const int warp_n = warp >> 1;   // 2 n-warps * 64 cols
    const int gid    = lane >> 2;   // 0..7
    const int tig    = lane & 3;    // 0..3
    const int blockRow = blockIdx.y * 128;
    const int blockCol = blockIdx.x * 128;

    float acc[4][8][4];
    #pragma unroll
    for (int mi = 0; mi < 4; mi++)
        #pragma unroll
        for (int ni = 0; ni < 8; ni++)
            #pragma unroll
            for (int e = 0; e < 4; e++) acc[mi][ni][e] = 0.0f;

    auto load_stage = [&](int chunk, int s) {
        const uint32_t abase = sbase + (uint32_t)(s * STAGE_F) * 4;
        const uint32_t bbase = abase + HALF_F * 4;
        int koff = chunk * 32;
        const float* Asrc;
        if (MODE == 3)          { Asrc = A0; }
        else if (koff < IN_DIM) { Asrc = A0; }
        else                    { Asrc = A1; koff -= IN_DIM; }
        #pragma unroll
        for (int i = 0; i < 8; i++) {                    // A: 1024 x 16B
            int idx = tid + i * 128;
            int r = idx >> 3, c = idx & 7;
            cp16(abase + (uint32_t)(r * ROWSTR + c * 4) * 4,
                 Asrc + (size_t)(blockRow + r) * 1024 + koff + c * 4);
        }
        #pragma unroll
        for (int i = 0; i < 8; i++) {                    // B(W): 1024 x 16B
            int idx = tid + i * 128;
            int r = idx >> 3, c = idx & 7;
            cp16(bbase + (uint32_t)(r * ROWSTR + c * 4) * 4,
                 W + (size_t)(blockCol + r) * KTOT + chunk * 32 + c * 4);
        }
        asm volatile("cp.async.commit_group;" ::: "memory");
    };

    // prologue: 2 stages in flight
    load_stage(0, 0);
    load_stage(1, 1);

    int s_cur = 0;                 // stage of chunk c
    for (int chunk = 0; chunk < NC; chunk++) {
        if (chunk + 1 < NC)
            asm volatile("cp.async.wait_group 1;" ::: "memory");
        else
            asm volatile("cp.async.wait_group 0;" ::: "memory");
        __syncthreads();

        // kick off chunk+2 into the stage consumed at chunk-1 (freed by the barrier)
        if (chunk + 2 < NC) {
            int s_next = s_cur + 2;
            if (s_next >= NSTAGE) s_next -= NSTAGE;
            load_stage(chunk + 2, s_next);
        }

        const float* As = smem + s_cur * STAGE_F;
        const float* Bs = As + HALF_F;

        #pragma unroll
        for (int ks = 0; ks < 4; ks++) {
            const int k = ks * 8;
            uint32_t af[4][4];
            #pragma unroll
            for (int mi = 0; mi < 4; mi++) {
                int rb = warp_m * 64 + mi * 16;
                af[mi][0] = f2tf32(As[(rb + gid    ) * ROWSTR + k + tig    ]);
                af[mi][1] = f2tf32(As[(rb + gid + 8) * ROWSTR + k + tig    ]);
                af[mi][2] = f2tf32(As[(rb + gid    ) * ROWSTR + k + tig + 4]);
                af[mi][3] = f2tf32(As[(rb + gid + 8) * ROWSTR + k + tig + 4]);
            }
            uint32_t bf[8][2];
            #pragma unroll
            for (int ni = 0; ni < 8; ni++) {
                int cb = warp_n * 64 + ni * 8;
                bf[ni][0] = f2tf32(Bs[(cb + gid) * ROWSTR + k + tig    ]);
                bf[ni][1] = f2tf32(Bs[(cb + gid) * ROWSTR + k + tig + 4]);
            }
            #pragma unroll
            for (int mi = 0; mi < 4; mi++)
                #pragma unroll
                for (int ni = 0; ni < 8; ni++) {
                    asm volatile(
                        "mma.sync.aligned.m16n8k8.row.col.f32.tf32.tf32.f32 "
                        "{%0,%1,%2,%3}, {%4,%5,%6,%7}, {%8,%9}, {%0,%1,%2,%3};"
                        : "+f"(acc[mi][ni][0]), "+f"(acc[mi][ni][1]),
                          "+f"(acc[mi][ni][2]), "+f"(acc[mi][ni][3])
                        : "r"(af[mi][0]), "r"(af[mi][1]),
                          "r"(af[mi][2]), "r"(af[mi][3]),
                          "r"(bf[ni][0]), "r"(bf[ni][1]));
                }
        }

        s_cur++;
        if (s_cur == NSTAGE) s_cur = 0;
    }

    // ---------------- fused epilogue ------------------------------------------
    #pragma unroll
    for (int mi = 0; mi < 4; mi++) {
        #pragma unroll
        for (int ni = 0; ni < 8; ni++) {
            const int col = blockCol + warp_n * 64 + ni * 8 + tig * 2;
            float2 bv = *(const float2*)(bias + col);
            #pragma unroll
            for (int half = 0; half < 2; half++) {
                const int row = blockRow + warp_m * 64 + mi * 16 + gid + half * 8;
                float v0 = acc[mi][ni][half * 2 + 0] + bv.x;
                float v1 = acc[mi][ni][half * 2 + 1] + bv.y;
                if (MODE == 0) {
                    *(float2*)(g_z + (size_t)row * H_DIM + col) =
                        make_float2(sigmoidf_(v0), sigmoidf_(v1));
                } else if (MODE == 1) {
                    float2 hv = *(const float2*)(hprev + (size_t)row * H_DIM + col);
                    *(float2*)(g_rh + (size_t)row * H_DIM + col) =
                        make_float2(sigmoidf_(v0) * hv.x, sigmoidf_(v1) * hv.y);
                } else if (MODE == 2) {
                    float2 hv = *(const float2*)(hprev + (size_t)row * H_DIM + col);
                    float2 zv = *(const float2*)(g_z   + (size_t)row * H_DIM + col);
                    float h0 = (1.0f - zv.x) * hv.x + zv.x * tanhf(v0);
                    float h1 = (1.0f - zv.y) * hv.y + zv.y * tanhf(v1);
                    *(float2*)(out   + (size_t)row * H_DIM + col) = make_float2(h0, h1);
                    *(float2*)(g_hid + (size_t)row * H_DIM + col) = make_float2(h0, h1);
                } else {
                    *(float2*)(out + (size_t)row * OUT_DIM + col) = make_float2(v0, v1);
                }
            }
        }
    }
}

// ---------- host ---------------------------------------------------------------
extern "C" void kernel_launch(void* const* d_in, const int* in_sizes, int n_in,
                              void* d_out, int out_size)
{
    const float* x  = (const float*)d_in[0];
    const float* h  = (const float*)d_in[1];
    const float* Wz = (const float*)d_in[2];
    const float* bz = (const float*)d_in[3];
    const float* Wr = (const float*)d_in[4];
    const float* br = (const float*)d_in[5];
    const float* Wh = (const float*)d_in[6];
    const float* bh = (const float*)d_in[7];
    const float* Wo = (const float*)d_in[8];
    const float* bo = (const float*)d_in[9];

    float* out_o = (float*)d_out;
    float* out_h = (float*)d_out + (size_t)BB * OUT_DIM;

    static bool attr_done = false;
    if (!attr_done) {
        cudaFuncSetAttribute(hgemm<0>, cudaFuncAttributeMaxDynamicSharedMemorySize, SMEM_BYTES);
        cudaFuncSetAttribute(hgemm<1>, cudaFuncAttributeMaxDynamicSharedMemorySize, SMEM_BYTES);
        cudaFuncSetAttribute(hgemm<2>, cudaFuncAttributeMaxDynamicSharedMemorySize, SMEM_BYTES);
        cudaFuncSetAttribute(hgemm<3>, cudaFuncAttributeMaxDynamicSharedMemorySize, SMEM_BYTES);
        attr_done = true;
    }

    float* g_rh_p;  cudaGetSymbolAddress((void**)&g_rh_p,  g_rh);
    float* g_hid_p; cudaGetSymbolAddress((void**)&g_hid_p, g_hid);

    dim3 blk(128);
    dim3 g1(H_DIM / 128, BB / 128);    // (8, 64)
    dim3 g3(OUT_DIM / 128, BB / 128);  // (4, 64)

    dummy_k<<<1, 32>>>();   // pad so profiler's capture slot (idx 3) = big MODE-2 GEMM

    // z = sigmoid([x|h] Wz^T + bz)
    hgemm<0><<<g1, blk, SMEM_BYTES>>>(x, h, Wz, bz, nullptr, nullptr);
    // rh = sigmoid([x|h] Wr^T + br) * h
    hgemm<1><<<g1, blk, SMEM_BYTES>>>(x, h, Wr, br, h, nullptr);
    // hidden = (1-z)*h + z*tanh([x|rh] Wh^T + bh)   (captured by profiler)
    hgemm<2><<<g1, blk, SMEM_BYTES>>>(x, g_rh_p, Wh, bh, h, out_h);
    // output = hidden Wo^T + bo
    hgemm<3><<<g3, blk, SMEM_BYTES>>>(g_hid_p, nullptr, Wo, bo, nullptr, out_o);
}

// round 6
// speedup vs baseline: 1.5761x; 1.0898x over previous
#include <cuda_runtime.h>
#include <cstdint>
#include <cstddef>

#define BB      8192
#define IN_DIM  1024
#define H_DIM   1024
#define OUT_DIM 512
#define KBIG    (IN_DIM + H_DIM)

// ---------- scratch (__device__ globals: allocation-guard-safe) ----------------
__device__ float g_z  [BB * H_DIM];     // sigmoid(z)
__device__ float g_rh [BB * H_DIM];     // r * h
__device__ float g_hid[BB * H_DIM];     // new hidden state (copy of out_h)

// ---------- helpers ------------------------------------------------------------
__device__ __forceinline__ uint32_t smem_u32(const void* p) {
    uint32_t a;
    asm("{ .reg .u64 t; cvta.to.shared.u64 t, %1; cvt.u32.u64 %0, t; }" : "=r"(a) : "l"(p));
    return a;
}
__device__ __forceinline__ uint32_t f2tf32(float f) {
    uint32_t r;
    asm("cvt.rna.tf32.f32 %0, %1;" : "=r"(r) : "f"(f));
    return r;
}
__device__ __forceinline__ float sigmoidf_(float x) { return 1.0f / (1.0f + expf(-x)); }

__device__ __forceinline__ void cp16(uint32_t dst, const void* src) {
    asm volatile("cp.async.cg.shared.global [%0], [%1], 16;" :: "r"(dst), "l"(src));
}

// pad launches so the profiler's fixed capture slot (launch idx 3) = MODE-2 GEMM
__global__ void dummy_k() {}

// ---------- HMMA GEMM + fused GRU epilogue -------------------------------------
// CTA tile 128x128, 128 threads = 4 warps (2m x 2n), warp tile 64x64.
// K in 32-float chunks, 3-stage cp.async pipeline, ONE barrier per chunk,
// fragment double-buffering inside the chunk (prefetch k-step s+1 during s).
// MODE 0: merged z+r (gridDim.z=2 selects weights/epilogue). MODE 2, 3 as before.
#define ROWSTR   36
#define HALF_F   (128 * ROWSTR)                 // 4608 floats (A or B half)
#define STAGE_F  (2 * HALF_F)                   // 9216 floats
#define NSTAGE   3
#define SMEM_BYTES (NSTAGE * STAGE_F * 4)       // 110592 bytes

template<int MODE>
__global__ __launch_bounds__(128, 2)
void hgemm(const float* __restrict__ A0, const float* __restrict__ A1,
           const float* __restrict__ Wa, const float* __restrict__ Wb,
           const float* __restrict__ biasa, const float* __restrict__ biasb,
           const float* __restrict__ hprev, float* __restrict__ out)
{
    constexpr int KTOT = (MODE == 3) ? H_DIM : KBIG;
    constexpr int NC   = KTOT / 32;

    extern __shared__ float smem[];
    const uint32_t sbase = smem_u32(smem);

    const int tid    = threadIdx.x;
    const int lane   = tid & 31;
    const int warp   = tid >> 5;
    const int warp_m = warp & 1;    // 2 m-warps * 64 rows
    const int warp_n = warp >> 1;   // 2 n-warps * 64 cols
    const int gid    = lane >> 2;   // 0..7
    const int tig    = lane & 3;    // 0..3
    const int blockRow = blockIdx.y * 128;
    const int blockCol = blockIdx.x * 128;

    const bool alt = (MODE == 0) && (blockIdx.z != 0);
    const float* W    = alt ? Wb    : Wa;
    const float* bias = alt ? biasb : biasa;

    float acc[4][8][4];
    #pragma unroll
    for (int mi = 0; mi < 4; mi++)
        #pragma unroll
        for (int ni = 0; ni < 8; ni++)
            #pragma unroll
            for (int e = 0; e < 4; e++) acc[mi][ni][e] = 0.0f;

    auto load_stage = [&](int chunk, int s) {
        const uint32_t abase = sbase + (uint32_t)(s * STAGE_F) * 4;
        const uint32_t bbase = abase + HALF_F * 4;
        int koff = chunk * 32;
        const float* Asrc;
        if (MODE == 3)          { Asrc = A0; }
        else if (koff < IN_DIM) { Asrc = A0; }
        else                    { Asrc = A1; koff -= IN_DIM; }
        #pragma unroll
        for (int i = 0; i < 8; i++) {                    // A: 1024 x 16B
            int idx = tid + i * 128;
            int r = idx >> 3, c = idx & 7;
            cp16(abase + (uint32_t)(r * ROWSTR + c * 4) * 4,
                 Asrc + (size_t)(blockRow + r) * 1024 + koff + c * 4);
        }
        #pragma unroll
        for (int i = 0; i < 8; i++) {                    // B(W): 1024 x 16B
            int idx = tid + i * 128;
            int r = idx >> 3, c = idx & 7;
            cp16(bbase + (uint32_t)(r * ROWSTR + c * 4) * 4,
                 W + (size_t)(blockCol + r) * KTOT + chunk * 32 + c * 4);
        }
        asm volatile("cp.async.commit_group;" ::: "memory");
    };

    // prologue: 2 stages in flight
    load_stage(0, 0);
    load_stage(1, 1);

    uint32_t af[2][4][4], bf[2][8][2];   // double-buffered fragments

    int s_cur = 0;
    for (int chunk = 0; chunk < NC; chunk++) {
        if (chunk + 1 < NC)
            asm volatile("cp.async.wait_group 1;" ::: "memory");
        else
            asm volatile("cp.async.wait_group 0;" ::: "memory");
        __syncthreads();

        const float* As = smem + s_cur * STAGE_F;
        const float* Bs = As + HALF_F;

        auto load_frags = [&](int ks, int b) {
            const int k = ks * 8;
            #pragma unroll
            for (int mi = 0; mi < 4; mi++) {
                int rb = warp_m * 64 + mi * 16;
                af[b][mi][0] = f2tf32(As[(rb + gid    ) * ROWSTR + k + tig    ]);
                af[b][mi][1] = f2tf32(As[(rb + gid + 8) * ROWSTR + k + tig    ]);
                af[b][mi][2] = f2tf32(As[(rb + gid    ) * ROWSTR + k + tig + 4]);
                af[b][mi][3] = f2tf32(As[(rb + gid + 8) * ROWSTR + k + tig + 4]);
            }
            #pragma unroll
            for (int ni = 0; ni < 8; ni++) {
                int cb = warp_n * 64 + ni * 8;
                bf[b][ni][0] = f2tf32(Bs[(cb + gid) * ROWSTR + k + tig    ]);
                bf[b][ni][1] = f2tf32(Bs[(cb + gid) * ROWSTR + k + tig + 4]);
            }
        };

        // first k-step fragments, then kick the chunk+2 gmem prefetch
        load_frags(0, 0);
        if (chunk + 2 < NC) {
            int s_next = s_cur + 2;
            if (s_next >= NSTAGE) s_next -= NSTAGE;
            load_stage(chunk + 2, s_next);
        }

        #pragma unroll
        for (int ks = 0; ks < 4; ks++) {
            const int b = ks & 1;
            if (ks < 3) load_frags(ks + 1, b ^ 1);   // overlap with HMMAs below
            #pragma unroll
            for (int mi = 0; mi < 4; mi++)
                #pragma unroll
                for (int ni = 0; ni < 8; ni++) {
                    asm volatile(
                        "mma.sync.aligned.m16n8k8.row.col.f32.tf32.tf32.f32 "
                        "{%0,%1,%2,%3}, {%4,%5,%6,%7}, {%8,%9}, {%0,%1,%2,%3};"
                        : "+f"(acc[mi][ni][0]), "+f"(acc[mi][ni][1]),
                          "+f"(acc[mi][ni][2]), "+f"(acc[mi][ni][3])
                        : "r"(af[b][mi][0]), "r"(af[b][mi][1]),
                          "r"(af[b][mi][2]), "r"(af[b][mi][3]),
                          "r"(bf[b][ni][0]), "r"(bf[b][ni][1]));
                }
        }

        s_cur++;
        if (s_cur == NSTAGE) s_cur = 0;
    }

    // ---------------- fused epilogue ------------------------------------------
    #pragma unroll
    for (int mi = 0; mi < 4; mi++) {
        #pragma unroll
        for (int ni = 0; ni < 8; ni++) {
            const int col = blockCol + warp_n * 64 + ni * 8 + tig * 2;
            float2 bv = *(const float2*)(bias + col);
            #pragma unroll
            for (int half = 0; half < 2; half++) {
                const int row = blockRow + warp_m * 64 + mi * 16 + gid + half * 8;
                float v0 = acc[mi][ni][half * 2 + 0] + bv.x;
                float v1 = acc[mi][ni][half * 2 + 1] + bv.y;
                if (MODE == 0) {
                    if (!alt) {                       // z gate
                        *(float2*)(g_z + (size_t)row * H_DIM + col) =
                            make_float2(sigmoidf_(v0), sigmoidf_(v1));
                    } else {                          // r gate -> r*h
                        float2 hv = *(const float2*)(hprev + (size_t)row * H_DIM + col);
                        *(float2*)(g_rh + (size_t)row * H_DIM + col) =
                            make_float2(sigmoidf_(v0) * hv.x, sigmoidf_(v1) * hv.y);
                    }
                } else if (MODE == 2) {
                    float2 hv = *(const float2*)(hprev + (size_t)row * H_DIM + col);
                    float2 zv = *(const float2*)(g_z   + (size_t)row * H_DIM + col);
                    float h0 = (1.0f - zv.x) * hv.x + zv.x * tanhf(v0);
                    float h1 = (1.0f - zv.y) * hv.y + zv.y * tanhf(v1);
                    *(float2*)(out   + (size_t)row * H_DIM + col) = make_float2(h0, h1);
                    *(float2*)(g_hid + (size_t)row * H_DIM + col) = make_float2(h0, h1);
                } else {
                    *(float2*)(out + (size_t)row * OUT_DIM + col) = make_float2(v0, v1);
                }
            }
        }
    }
}

// ---------- host ---------------------------------------------------------------
extern "C" void kernel_launch(void* const* d_in, const int* in_sizes, int n_in,
                              void* d_out, int out_size)
{
    const float* x  = (const float*)d_in[0];
    const float* h  = (const float*)d_in[1];
    const float* Wz = (const float*)d_in[2];
    const float* bz = (const float*)d_in[3];
    const float* Wr = (const float*)d_in[4];
    const float* br = (const float*)d_in[5];
    const float* Wh = (const float*)d_in[6];
    const float* bh = (const float*)d_in[7];
    const float* Wo = (const float*)d_in[8];
    const float* bo = (const float*)d_in[9];

    float* out_o = (float*)d_out;
    float* out_h = (float*)d_out + (size_t)BB * OUT_DIM;

    static bool attr_done = false;
    if (!attr_done) {
        cudaFuncSetAttribute(hgemm<0>, cudaFuncAttributeMaxDynamicSharedMemorySize, SMEM_BYTES);
        cudaFuncSetAttribute(hgemm<2>, cudaFuncAttributeMaxDynamicSharedMemorySize, SMEM_BYTES);
        cudaFuncSetAttribute(hgemm<3>, cudaFuncAttributeMaxDynamicSharedMemorySize, SMEM_BYTES);
        attr_done = true;
    }

    float* g_rh_p;  cudaGetSymbolAddress((void**)&g_rh_p,  g_rh);
    float* g_hid_p; cudaGetSymbolAddress((void**)&g_hid_p, g_hid);

    dim3 blk(128);
    dim3 gzr(H_DIM / 128, BB / 128, 2);  // (8, 64, 2): z and r in one launch
    dim3 g1(H_DIM / 128, BB / 128);      // (8, 64)
    dim3 g3(OUT_DIM / 128, BB / 128);    // (4, 64)

    dummy_k<<<1, 32>>>();   // pad: launches = d,d,zr,g2(idx3, captured),g3
    dummy_k<<<1, 32>>>();

    // z = sigmoid([x|h] Wz^T + bz);  rh = sigmoid([x|h] Wr^T + br) * h
    hgemm<0><<<gzr, blk, SMEM_BYTES>>>(x, h, Wz, Wr, bz, br, h, nullptr);
    // hidden = (1-z)*h + z*tanh([x|rh] Wh^T + bh)
    hgemm<2><<<g1, blk, SMEM_BYTES>>>(x, g_rh_p, Wh, nullptr, bh, nullptr, h, out_h);
    // output = hidden Wo^T + bo
    hgemm<3><<<g3, blk, SMEM_BYTES>>>(g_hid_p, nullptr, Wo, nullptr, bo, nullptr, nullptr, out_o);
}